// round 9
// baseline (speedup 1.0000x reference)
#include <cuda_runtime.h>
#include <cuda_fp16.h>
#include <cstdint>

// ---------------- problem constants ----------------
#define HW    50176          // 224*224 (= 1024 windows * 49)
#define NTILE 392            // HW / 128

// scratch  (qkv padded by 64 halves: attention's aligned-span loads may
// read up to 15 halves past the last window run; values are discarded)
__device__ __half g_qkvh[77070400];  // [4][384][p' window-major] fp16
__device__ __half g_xh[25690112];    // x tiles [4*392][n=128 (p')][k=128] fp16
__device__ __half g_ah[25690112];    // attn-out tiles [4*392][n=128 (row-major pixel)][k=128]
__device__ __half g_wh[65536];       // w_qkv (384 rows) then w_out (128 rows), [row][128]

// ---------------- helpers ----------------
__device__ __forceinline__ uint32_t smem_u32(const void* p){
    uint32_t a;
    asm("{ .reg .u64 t; cvta.to.shared.u64 t, %1; cvt.u32.u64 %0, t; }" : "=r"(a) : "l"(p));
    return a;
}
__device__ __forceinline__ uint32_t pack_h2(float a, float b){
    __half2 h = __floats2half2_rn(a, b);
    return *(uint32_t*)&h;
}

#define LDSM_X4(r0, r1, r2, r3, addr)                                                     \
    asm volatile("ldmatrix.sync.aligned.m8n8.x4.shared.b16 {%0,%1,%2,%3}, [%4];"          \
        : "=r"(r0), "=r"(r1), "=r"(r2), "=r"(r3) : "r"(addr))

#define LDSM_X4T(r0, r1, r2, r3, addr)                                                    \
    asm volatile("ldmatrix.sync.aligned.m8n8.x4.trans.shared.b16 {%0,%1,%2,%3}, [%4];"    \
        : "=r"(r0), "=r"(r1), "=r"(r2), "=r"(r3) : "r"(addr))

#define MMA_F16(d, a, b0, b1)                                                             \
    asm volatile("mma.sync.aligned.m16n8k16.row.col.f32.f16.f16.f32 "                     \
        "{%0,%1,%2,%3}, {%4,%5,%6,%7}, {%8,%9}, {%0,%1,%2,%3};"                           \
        : "+f"((d)[0]), "+f"((d)[1]), "+f"((d)[2]), "+f"((d)[3])                          \
        : "r"((a)[0]), "r"((a)[1]), "r"((a)[2]), "r"((a)[3]), "r"(b0), "r"(b1))

// =====================================================================
// weight fp32 -> fp16 (one-shot, tiny)
// =====================================================================
__global__ void wconv(const float* __restrict__ W, __half* __restrict__ Wh, int n4)
{
    int i = blockIdx.x * 256 + threadIdx.x;
    if (i >= n4) return;
    float4 v = ((const float4*)W)[i];
    *(uint2*)(Wh + i*4) = make_uint2(pack_h2(v.x, v.y), pack_h2(v.z, v.w));
}

// =====================================================================
// x -> window-major fp16 tiles: tile[n][k], n = window-major pixel p'
// =====================================================================
#define XS 131
#define XCONV_SMEM (128*XS*4 + 512)
__global__ __launch_bounds__(256)
void xconv(const float* __restrict__ X, __half* __restrict__ Xh)
{
    extern __shared__ char xsm[];
    float* ts  = (float*)xsm;                 // [k 128][XS] indexed by n
    int*   pix = (int*)(xsm + 128*XS*4);
    const int tid = threadIdx.x;
    const int bt = blockIdx.x;
    const int b = bt / NTILE, t = bt - b * NTILE;

    if (tid < 128){
        int n = t * 128 + tid;                // window-major pixel id
        int w = n / 49, l = n - w * 49;
        int y = (w >> 5) * 7 + l / 7;
        int x = (w & 31) * 7 + l % 7;
        pix[tid] = y * 224 + x;
    }
    __syncthreads();

    const float* xb = X + (size_t)b * 128 * HW;
    {
        int nl = tid & 127;
        int k0 = tid >> 7;
        int p  = pix[nl];
        #pragma unroll 8
        for (int i = 0; i < 64; i++){
            int k = k0 + i * 2;
            ts[k * XS + nl] = xb[(size_t)k * HW + p];
        }
    }
    __syncthreads();

    size_t ob = (size_t)bt << 14;
    #pragma unroll
    for (int i = 0; i < 8; i++){
        int idx = tid + i * 256;
        int n = idx >> 4, kc = idx & 15;
        uint32_t r[4];
        #pragma unroll
        for (int j = 0; j < 4; j++){
            float v0 = ts[(kc*8 + 2*j    ) * XS + n];
            float v1 = ts[(kc*8 + 2*j + 1) * XS + n];
            r[j] = pack_h2(v0, v1);
        }
        *(uint4*)(Xh + ob + n*128 + kc*8) = make_uint4(r[0], r[1], r[2], r[3]);
    }
}

// =====================================================================
// fp16 mma.sync GEMM: Out[b][m][n] = sum_k W[m][k]*B[n][k] + bias[m]
// grid = (m-tiles, NTILE, 4): adjacent CTAs share the B tile (L2 reuse).
// =====================================================================
#define ASTRIDE 272
#define OFF_B   (128*ASTRIDE)
#define GEMM_SMEM (2*128*ASTRIDE)  // 69632

__global__ __launch_bounds__(256, 2)
void gemm_tc(const __half* __restrict__ Wh, int wofs,
             const __half* __restrict__ Bt,
             const float* __restrict__ bias, void* __restrict__ OutV,
             int Mtot, int fp16out)
{
    extern __shared__ char sm[];
    const uint32_t sb = smem_u32(sm);
    const int tid  = threadIdx.x;
    const int wid  = tid >> 5;
    const int lane = tid & 31;
    const int m0t    = blockIdx.x * 128;     // m-tile fastest -> B-tile L2 reuse
    const int nt_blk = blockIdx.y;
    const int b      = blockIdx.z;

    const __half* wp = Wh + wofs + (size_t)m0t * 128;
    const __half* bp = Bt + (((size_t)(b * NTILE + nt_blk)) << 14);

    #pragma unroll
    for (int i = 0; i < 8; i++){
        int idx = tid + i * 256;
        int row = idx >> 4, piece = idx & 15;
        *(uint4*)(sm + row * ASTRIDE + piece * 16) = *(const uint4*)(wp + row * 128 + piece * 8);
    }
    #pragma unroll
    for (int i = 0; i < 8; i++){
        int idx = tid + i * 256;
        int row = idx >> 4, piece = idx & 15;
        *(uint4*)(sm + OFF_B + row * ASTRIDE + piece * 16) = *(const uint4*)(bp + idx * 8);
    }
    __syncthreads();

    const int m0w = (wid >> 1) * 32;
    const int n0w = (wid & 1) * 64;
    const int row8 = lane & 7, quad = lane >> 3;

    uint32_t aoff[2], boff[2];
    #pragma unroll
    for (int mt = 0; mt < 2; mt++)
        aoff[mt] = sb + (uint32_t)((m0w + mt*16 + ((quad & 1) << 3) + row8) * ASTRIDE + ((quad >> 1) << 4));
    #pragma unroll
    for (int g = 0; g < 2; g++)
        boff[g] = sb + OFF_B + (uint32_t)((n0w + g*32 + (quad << 3) + row8) * ASTRIDE);

    float acc[2][8][4];
    #pragma unroll
    for (int mt = 0; mt < 2; mt++)
        #pragma unroll
        for (int nt = 0; nt < 8; nt++)
            #pragma unroll
            for (int q = 0; q < 4; q++) acc[mt][nt][q] = 0.f;

    #pragma unroll
    for (int ks = 0; ks < 8; ks++){
        const uint32_t kb = ks * 32;
        uint32_t af[2][4], bf[2][2][4];
        #pragma unroll
        for (int mt = 0; mt < 2; mt++)
            LDSM_X4(af[mt][0], af[mt][1], af[mt][2], af[mt][3], aoff[mt] + kb);
        #pragma unroll
        for (int g = 0; g < 2; g++){
            LDSM_X4(bf[g][0][0], bf[g][0][1], bf[g][0][2], bf[g][0][3], boff[g] + kb);
            LDSM_X4(bf[g][1][0], bf[g][1][1], bf[g][1][2], bf[g][1][3], boff[g] + kb + 16);
        }
        #pragma unroll
        for (int mt = 0; mt < 2; mt++)
            #pragma unroll
            for (int nt = 0; nt < 8; nt++){
                int g = nt >> 2, j = nt & 3;
                MMA_F16(acc[mt][nt], af[mt], bf[g][0][j], bf[g][1][j]);
            }
    }

    const int n0t = nt_blk * 128;
    #pragma unroll
    for (int mt = 0; mt < 2; mt++){
        int r0 = m0w + mt*16 + (lane >> 2);
        float bv0 = bias[m0t + r0];
        float bv1 = bias[m0t + r0 + 8];
        #pragma unroll
        for (int nt = 0; nt < 8; nt++){
            int col = n0t + n0w + nt*8 + ((lane & 3) << 1);
            if (fp16out){
                __half* OutH = (__half*)OutV;
                *(uint32_t*)(OutH + ((size_t)(b * Mtot + m0t + r0)    ) * HW + col) =
                    pack_h2(acc[mt][nt][0] + bv0, acc[mt][nt][1] + bv0);
                *(uint32_t*)(OutH + ((size_t)(b * Mtot + m0t + r0 + 8)) * HW + col) =
                    pack_h2(acc[mt][nt][2] + bv1, acc[mt][nt][3] + bv1);
            } else {
                float* Out = (float*)OutV;
                *(float2*)(Out + ((size_t)(b * Mtot + m0t + r0)    ) * HW + col) =
                    make_float2(acc[mt][nt][0] + bv0, acc[mt][nt][1] + bv0);
                *(float2*)(Out + ((size_t)(b * Mtot + m0t + r0 + 8)) * HW + col) =
                    make_float2(acc[mt][nt][2] + bv1, acc[mt][nt][3] + bv1);
            }
        }
    }
}

// =====================================================================
// warp-per-head windowed attention: one CTA (256 thr) per window, warp = head.
// Vectorized loads: per channel, the 49-half run [49w,49w+49) sits inside the
// 16B-aligned 64-half span at (49w & ~7); load 8 uint4 and predicate the scatter.
// =====================================================================
#define PH 136                     // smem pitch in halves (272B, conflict-free ldmatrix)
#define ATT_SMEM (3*64*PH*2)       // 52224

__global__ __launch_bounds__(256)
void attn_mma(const __half* __restrict__ qkv, __half* __restrict__ Ah)
{
    extern __shared__ __half asm_[];
    __half* qsm = asm_;                // [pos 64][128 c], pitch PH; reused as out-stage
    __half* ksm = asm_ + 64*PH;
    __half* vsm = asm_ + 128*PH;

    const int tid  = threadIdx.x;
    const int lane = tid & 31;
    const int wrp  = tid >> 5;         // head
    const int wi   = blockIdx.x;
    const int b    = wi >> 10;
    const int w    = wi & 1023;
    const int prow = (w >> 5) * 7, pcol = (w & 31) * 7;

    // zero pad rows 49..63 of q/k/v (NaN-safety for masked lanes)
    if (tid < 255){
        ((uint4*)(qsm + 49*PH))[tid] = make_uint4(0,0,0,0);
        ((uint4*)(ksm + 49*PH))[tid] = make_uint4(0,0,0,0);
        ((uint4*)(vsm + 49*PH))[tid] = make_uint4(0,0,0,0);
    }

    // ---- vectorized loads ----
    const int w49    = w * 49;
    const int astart = w49 & ~7;             // 16B-aligned span start (halves)
    const int off0   = astart - w49;         // -7..0
    const __half* qp = qkv + (size_t)(b * 384      ) * HW;
    const __half* kp = qkv + (size_t)(b * 384 + 128) * HW;
    const __half* vp = qkv + (size_t)(b * 384 + 256) * HW;
    const __half hscale = __float2half(0.25f);   // 1/sqrt(16), exact

    #pragma unroll
    for (int i = 0; i < 4; i++){
        int idx = tid + i * 256;              // 0..1023
        int c = idx >> 3, piece = idx & 7;
        int p0 = off0 + piece * 8;
        size_t ga = (size_t)c * HW + astart + piece * 8;

        uint4 vq = *(const uint4*)(qp + ga);
        __half* hq = (__half*)&vq;
        #pragma unroll
        for (int j = 0; j < 8; j++){
            int p = p0 + j;
            if ((unsigned)p < 49u) qsm[p*PH + c] = __hmul(hq[j], hscale);
        }
        uint4 vk = *(const uint4*)(kp + ga);
        __half* hk = (__half*)&vk;
        #pragma unroll
        for (int j = 0; j < 8; j++){
            int p = p0 + j;
            if ((unsigned)p < 49u) ksm[p*PH + c] = hk[j];
        }
        uint4 vv = *(const uint4*)(vp + ga);
        __half* hv = (__half*)&vv;
        #pragma unroll
        for (int j = 0; j < 8; j++){
            int p = p0 + j;
            if ((unsigned)p < 49u) vsm[p*PH + c] = hv[j];
        }
    }
    __syncthreads();

    const uint32_t qsb = smem_u32(qsm), ksb = smem_u32(ksm), vsb = smem_u32(vsm);
    const int row8 = lane & 7, quad = lane >> 3;
    const int cbase = 2 * (lane & 3);
    const uint32_t hoff = (uint32_t)wrp * 32;    // head byte offset in a row

    // K fragments: 64 m-rows x 16 k (this head's channels), loaded once
    uint32_t kf[2][2][4];
    #pragma unroll
    for (int g = 0; g < 2; g++){
        uint32_t ba = ksb + (uint32_t)((g*32 + quad*8 + row8) * (PH*2)) + hoff;
        LDSM_X4(kf[g][0][0], kf[g][0][1], kf[g][0][2], kf[g][0][3], ba);
        LDSM_X4(kf[g][1][0], kf[g][1][1], kf[g][1][2], kf[g][1][3], ba + 16);
    }
    // V^T fragments: 4 ksteps x 16 c
    uint32_t vf[4][4];
    #pragma unroll
    for (int ksp = 0; ksp < 4; ksp++){
        uint32_t va = vsb + (uint32_t)((ksp*16 + (lane & 15)) * (PH*2)) + hoff + ((lane >> 4) << 4);
        LDSM_X4T(vf[ksp][0], vf[ksp][1], vf[ksp][2], vf[ksp][3], va);
    }

    __half* ost = qsm;   // out-stage: warp-private column slice [*, wrp*16 .. +16)

    #pragma unroll
    for (int lt = 0; lt < 4; lt++){
        const int l0 = lt * 16;
        uint32_t af[4];
        LDSM_X4(af[0], af[1], af[2], af[3],
                qsb + (uint32_t)((l0 + ((quad & 1) << 3) + row8) * (PH*2)) + hoff + ((quad >> 1) << 4));

        // S = Q . K^T  (16 rows x 64 cols, in registers)
        float sc[8][4];
        #pragma unroll
        for (int nt = 0; nt < 8; nt++){
            sc[nt][0] = sc[nt][1] = sc[nt][2] = sc[nt][3] = 0.f;
            int g = nt >> 2, j = nt & 3;
            MMA_F16(sc[nt], af, kf[g][0][j], kf[g][1][j]);
        }

        // mask cols >= 49, row max (rows r and r+8 separate)
        float mx0 = -1e30f, mx1 = -1e30f;
        #pragma unroll
        for (int nt = 0; nt < 8; nt++){
            int col0 = nt*8 + cbase;
            if (col0 > 48){ sc[nt][0] = -1e30f; sc[nt][2] = -1e30f; }
            if (col0 + 1 > 48){ sc[nt][1] = -1e30f; sc[nt][3] = -1e30f; }
            mx0 = fmaxf(mx0, fmaxf(sc[nt][0], sc[nt][1]));
            mx1 = fmaxf(mx1, fmaxf(sc[nt][2], sc[nt][3]));
        }
        mx0 = fmaxf(mx0, __shfl_xor_sync(0xffffffffu, mx0, 1));
        mx0 = fmaxf(mx0, __shfl_xor_sync(0xffffffffu, mx0, 2));
        mx1 = fmaxf(mx1, __shfl_xor_sync(0xffffffffu, mx1, 1));
        mx1 = fmaxf(mx1, __shfl_xor_sync(0xffffffffu, mx1, 2));

        float s0 = 0.f, s1 = 0.f;
        #pragma unroll
        for (int nt = 0; nt < 8; nt++){
            sc[nt][0] = __expf(sc[nt][0] - mx0);
            sc[nt][1] = __expf(sc[nt][1] - mx0);
            sc[nt][2] = __expf(sc[nt][2] - mx1);
            sc[nt][3] = __expf(sc[nt][3] - mx1);
            s0 += sc[nt][0] + sc[nt][1];
            s1 += sc[nt][2] + sc[nt][3];
        }
        s0 += __shfl_xor_sync(0xffffffffu, s0, 1);
        s0 += __shfl_xor_sync(0xffffffffu, s0, 2);
        s1 += __shfl_xor_sync(0xffffffffu, s1, 1);
        s1 += __shfl_xor_sync(0xffffffffu, s1, 2);
        float inv0 = 1.f / s0, inv1 = 1.f / s1;

        // O = P . V  (C-frag of S == A-frag of P)
        float oc[2][4];
        oc[0][0]=oc[0][1]=oc[0][2]=oc[0][3]=0.f;
        oc[1][0]=oc[1][1]=oc[1][2]=oc[1][3]=0.f;
        #pragma unroll
        for (int ksp = 0; ksp < 4; ksp++){
            uint32_t pf[4];
            pf[0] = pack_h2(sc[2*ksp  ][0]*inv0, sc[2*ksp  ][1]*inv0);
            pf[1] = pack_h2(sc[2*ksp  ][2]*inv1, sc[2*ksp  ][3]*inv1);
            pf[2] = pack_h2(sc[2*ksp+1][0]*inv0, sc[2*ksp+1][1]*inv0);
            pf[3] = pack_h2(sc[2*ksp+1][2]*inv1, sc[2*ksp+1][3]*inv1);
            MMA_F16(oc[0], pf, vf[ksp][0], vf[ksp][1]);
            MMA_F16(oc[1], pf, vf[ksp][2], vf[ksp][3]);
        }

        // stage O rows (warp-private cols)
        int pr = l0 + (lane >> 2);
        #pragma unroll
        for (int n = 0; n < 2; n++){
            if (pr < 49)
                *(uint32_t*)(ost + pr*PH + wrp*16 + n*8 + cbase) = pack_h2(oc[n][0], oc[n][1]);
            if (pr + 8 < 49)
                *(uint32_t*)(ost + (pr+8)*PH + wrp*16 + n*8 + cbase) = pack_h2(oc[n][2], oc[n][3]);
        }
    }
    __syncthreads();

    // coalesced writeback: 49 pos x 128 c = 784 uint4
    for (int idx = tid; idx < 784; idx += 256){
        int p = idx >> 4, ch = idx & 15;
        int pix = (prow + p / 7) * 224 + pcol + (p % 7);
        int t = pix >> 7, n = pix & 127;
        *(uint4*)(Ah + (((size_t)(b * NTILE + t)) * 128 + n) * 128 + ch*8) =
            *(const uint4*)(ost + p*PH + ch*8);
    }
}

// ---------------- launch ----------------
extern "C" void kernel_launch(void* const* d_in, const int* in_sizes, int n_in,
                              void* d_out, int out_size)
{
    const float* x     = (const float*)d_in[0];
    const float* w_qkv = (const float*)d_in[1];
    const float* b_qkv = (const float*)d_in[2];
    const float* w_out = (const float*)d_in[3];
    const float* b_out = (const float*)d_in[4];
    float* out = (float*)d_out;

    __half *qkvh, *xh, *ah, *wh;
    cudaGetSymbolAddress((void**)&qkvh, g_qkvh);
    cudaGetSymbolAddress((void**)&xh, g_xh);
    cudaGetSymbolAddress((void**)&ah, g_ah);
    cudaGetSymbolAddress((void**)&wh, g_wh);

    cudaFuncSetAttribute(xconv,    cudaFuncAttributeMaxDynamicSharedMemorySize, XCONV_SMEM);
    cudaFuncSetAttribute(gemm_tc,  cudaFuncAttributeMaxDynamicSharedMemorySize, GEMM_SMEM);
    cudaFuncSetAttribute(attn_mma, cudaFuncAttributeMaxDynamicSharedMemorySize, ATT_SMEM);

    wconv<<<48, 256>>>(w_qkv, wh, 12288);
    wconv<<<16, 256>>>(w_out, wh + 49152, 4096);
    xconv<<<4 * NTILE, 256, XCONV_SMEM>>>(x, xh);
    gemm_tc<<<dim3(3, NTILE, 4), 256, GEMM_SMEM>>>(wh, 0,     xh, b_qkv, qkvh, 384, 1);
    attn_mma<<<4096, 256, ATT_SMEM>>>(qkvh, ah);
    gemm_tc<<<dim3(1, NTILE, 4), 256, GEMM_SMEM>>>(wh, 49152, ah, b_out, out, 128, 0);
}

// round 11
// speedup vs baseline: 1.1037x; 1.1037x over previous
#include <cuda_runtime.h>
#include <cuda_fp16.h>
#include <cstdint>

// ---------------- problem constants ----------------
#define HW    50176          // 224*224 (= 1024 windows * 49)
#define NTILE 392            // HW / 128

// scratch  (qkv padded by 64 halves for attention's aligned-span loads)
__device__ __half g_qkvh[77070400];  // [4][384][p' window-major] fp16
__device__ __half g_xh[25690112];    // x tiles [4*392][n=128 (p')][k=128] fp16
__device__ __half g_ah[25690112];    // attn-out tiles [4*392][n=128 (row-major pixel)][k=128]
__device__ __half g_wh[65536];       // w_qkv (384 rows) then w_out (128 rows), [row][128]

// ---------------- helpers ----------------
__device__ __forceinline__ uint32_t smem_u32(const void* p){
    uint32_t a;
    asm("{ .reg .u64 t; cvta.to.shared.u64 t, %1; cvt.u32.u64 %0, t; }" : "=r"(a) : "l"(p));
    return a;
}
__device__ __forceinline__ uint32_t pack_h2(float a, float b){
    __half2 h = __floats2half2_rn(a, b);
    return *(uint32_t*)&h;
}

#define LDSM_X4(r0, r1, r2, r3, addr)                                                     \
    asm volatile("ldmatrix.sync.aligned.m8n8.x4.shared.b16 {%0,%1,%2,%3}, [%4];"          \
        : "=r"(r0), "=r"(r1), "=r"(r2), "=r"(r3) : "r"(addr))

#define LDSM_X4T(r0, r1, r2, r3, addr)                                                    \
    asm volatile("ldmatrix.sync.aligned.m8n8.x4.trans.shared.b16 {%0,%1,%2,%3}, [%4];"    \
        : "=r"(r0), "=r"(r1), "=r"(r2), "=r"(r3) : "r"(addr))

#define MMA_F16(d, a, b0, b1)                                                             \
    asm volatile("mma.sync.aligned.m16n8k16.row.col.f32.f16.f16.f32 "                     \
        "{%0,%1,%2,%3}, {%4,%5,%6,%7}, {%8,%9}, {%0,%1,%2,%3};"                           \
        : "+f"((d)[0]), "+f"((d)[1]), "+f"((d)[2]), "+f"((d)[3])                          \
        : "r"((a)[0]), "r"((a)[1]), "r"((a)[2]), "r"((a)[3]), "r"(b0), "r"(b1))

#define CP16(dst, src)                                                                    \
    asm volatile("cp.async.ca.shared.global [%0], [%1], 16;" :: "r"(dst), "l"(src) : "memory")
#define CP_COMMIT  asm volatile("cp.async.commit_group;" ::: "memory")
#define CP_WAIT(n) asm volatile("cp.async.wait_group %0;" :: "n"(n) : "memory")

// =====================================================================
// weight fp32 -> fp16 (one-shot, tiny)
// =====================================================================
__global__ void wconv(const float* __restrict__ W, __half* __restrict__ Wh, int n4)
{
    int i = blockIdx.x * 256 + threadIdx.x;
    if (i >= n4) return;
    float4 v = ((const float4*)W)[i];
    *(uint2*)(Wh + i*4) = make_uint2(pack_h2(v.x, v.y), pack_h2(v.z, v.w));
}

// =====================================================================
// xconv v2: band-wise coalesced transpose.
// grid (32 bands, 2 channel-halves, 4 b); CTA stages 16 ch x 1568 px (one
// 7-row band, contiguous in pixel space) with +8/row skew, then emits
// window-major [n][16c] fp16 as 32B sector-aligned stores.
// =====================================================================
#define XC_PITCH 1632
#define XCONV_SMEM (16*XC_PITCH*4)   // 104448
__global__ __launch_bounds__(256)
void xconv(const float* __restrict__ X, __half* __restrict__ Xh)
{
    extern __shared__ float ts[];    // [16][XC_PITCH], rows skewed by +8 per pixel-row
    const int tid  = threadIdx.x;
    const int band = blockIdx.x;     // 0..31 (7 global rows each)
    const int half = blockIdx.y;     // 0..1
    const int b    = blockIdx.z;
    const int ch0  = half * 64;

    #pragma unroll 1
    for (int g = 0; g < 4; g++){
        if (g) __syncthreads();
        const int cbase = ch0 + g * 16;

        // load: 16 channels x 1568 px, fully coalesced float4
        #pragma unroll
        for (int i = 0; i < 25; i++){
            int idx = tid + i * 256;              // float4 id, 0..6271
            if (idx < 6272){
                int c = idx / 392;                // 392 float4 per channel
                int j = idx - c * 392;
                float4 v = *(const float4*)(X + ((size_t)(b*128 + cbase + c)) * HW + band*1568 + j*4);
                int r = j / 56;                   // pixel row within band
                float* d = ts + c * XC_PITCH + j*4 + r*8;
                d[0] = v.x; d[1] = v.y; d[2] = v.z; d[3] = v.w;
            }
        }
        __syncthreads();

        // emit: each idx = (window lw, pos l); 32B store of 16 channels
        for (int idx = tid; idx < 1568; idx += 256){
            int lw = idx / 49;
            int l  = idx - lw * 49;
            int r  = l / 7;
            int q  = l - r * 7;
            int pb = r*224 + lw*7 + q + r*8;      // skewed smem pixel index
            uint32_t h[8];
            #pragma unroll
            for (int j = 0; j < 8; j++){
                float v0 = ts[(2*j  ) * XC_PITCH + pb];
                float v1 = ts[(2*j+1) * XC_PITCH + pb];
                h[j] = pack_h2(v0, v1);
            }
            int pg = (band*32 + lw) * 49 + l;     // global window-major pixel
            int t = pg >> 7, n = pg & 127;
            __half* o = Xh + (((size_t)(b*NTILE + t)) * 128 + n) * 128 + cbase;
            *(uint4*)(o)     = make_uint4(h[0], h[1], h[2], h[3]);
            *(uint4*)(o + 8) = make_uint4(h[4], h[5], h[6], h[7]);
        }
    }
}

// =====================================================================
// fp16 mma.sync GEMM with cp.async 2-chunk pipeline (K = 2 x 64).
// Out[b][m][n] = sum_k W[m][k]*B[n][k] + bias[m]
// =====================================================================
#define CPITCH 144                 // 64 fp16 = 128B + 16B pad (conflict-free ldmatrix)
#define STG_B  18432               // 128 rows * 144B
#define STGSZ  36864
#define GEMM_SMEM (2*STGSZ)        // 73728

__global__ __launch_bounds__(256, 2)
void gemm_tc(const __half* __restrict__ Wh, int wofs,
             const __half* __restrict__ Bt,
             const float* __restrict__ bias, void* __restrict__ OutV,
             int Mtot, int fp16out)
{
    extern __shared__ char sm[];
    const uint32_t sb = smem_u32(sm);
    const int tid  = threadIdx.x;
    const int wid  = tid >> 5;
    const int lane = tid & 31;
    const int nt_blk = blockIdx.x;
    const int m0t    = blockIdx.y * 128;
    const int b      = blockIdx.z;

    const __half* wp = Wh + wofs + (size_t)m0t * 128;
    const __half* bp = Bt + (((size_t)(b * NTILE + nt_blk)) << 14);

    // prefetch both K-chunks via cp.async (one commit group per chunk)
    // 1024 pieces per array per chunk: row = idx>>3 (0..127), piece = idx&7 (8 x 16B = 128B row)
    #pragma unroll
    for (int ch = 0; ch < 2; ch++){
        uint32_t s0 = sb + ch * STGSZ;
        #pragma unroll
        for (int i = 0; i < 4; i++){
            int idx = tid + i * 256;              // 0..1023
            int row = idx >> 3, piece = idx & 7;
            CP16(s0 + row * CPITCH + piece * 16, wp + row * 128 + ch * 64 + piece * 8);
        }
        #pragma unroll
        for (int i = 0; i < 4; i++){
            int idx = tid + i * 256;
            int row = idx >> 3, piece = idx & 7;
            CP16(s0 + STG_B + row * CPITCH + piece * 16, bp + row * 128 + ch * 64 + piece * 8);
        }
        CP_COMMIT;
    }

    const int m0w = (wid >> 1) * 32;
    const int n0w = (wid & 1) * 64;
    const int row8 = lane & 7, quad = lane >> 3;

    uint32_t aoff[2], boff[2];
    #pragma unroll
    for (int mt = 0; mt < 2; mt++)
        aoff[mt] = (uint32_t)((m0w + mt*16 + ((quad & 1) << 3) + row8) * CPITCH + ((quad >> 1) << 4));
    #pragma unroll
    for (int g = 0; g < 2; g++)
        boff[g] = (uint32_t)(STG_B + (n0w + g*32 + (quad << 3) + row8) * CPITCH);

    float acc[2][8][4];
    #pragma unroll
    for (int mt = 0; mt < 2; mt++)
        #pragma unroll
        for (int nt = 0; nt < 8; nt++)
            #pragma unroll
            for (int q = 0; q < 4; q++) acc[mt][nt][q] = 0.f;

    #pragma unroll
    for (int ch = 0; ch < 2; ch++){
        if (ch == 0) { CP_WAIT(1); } else { CP_WAIT(0); }
        __syncthreads();
        const uint32_t s0 = sb + ch * STGSZ;
        #pragma unroll
        for (int ks = 0; ks < 4; ks++){
            const uint32_t kb = ks * 32;
            uint32_t af[2][4], bf[2][2][4];
            #pragma unroll
            for (int mt = 0; mt < 2; mt++)
                LDSM_X4(af[mt][0], af[mt][1], af[mt][2], af[mt][3], s0 + aoff[mt] + kb);
            #pragma unroll
            for (int g = 0; g < 2; g++){
                LDSM_X4(bf[g][0][0], bf[g][0][1], bf[g][0][2], bf[g][0][3], s0 + boff[g] + kb);
                LDSM_X4(bf[g][1][0], bf[g][1][1], bf[g][1][2], bf[g][1][3], s0 + boff[g] + kb + 16);
            }
            #pragma unroll
            for (int mt = 0; mt < 2; mt++)
                #pragma unroll
                for (int nt = 0; nt < 8; nt++){
                    int g = nt >> 2, j = nt & 3;
                    MMA_F16(acc[mt][nt], af[mt], bf[g][0][j], bf[g][1][j]);
                }
        }
    }

    const int n0t = nt_blk * 128;
    #pragma unroll
    for (int mt = 0; mt < 2; mt++){
        int r0 = m0w + mt*16 + (lane >> 2);
        float bv0 = bias[m0t + r0];
        float bv1 = bias[m0t + r0 + 8];
        #pragma unroll
        for (int nt = 0; nt < 8; nt++){
            int col = n0t + n0w + nt*8 + ((lane & 3) << 1);
            if (fp16out){
                __half* OutH = (__half*)OutV;
                *(uint32_t*)(OutH + ((size_t)(b * Mtot + m0t + r0)    ) * HW + col) =
                    pack_h2(acc[mt][nt][0] + bv0, acc[mt][nt][1] + bv0);
                *(uint32_t*)(OutH + ((size_t)(b * Mtot + m0t + r0 + 8)) * HW + col) =
                    pack_h2(acc[mt][nt][2] + bv1, acc[mt][nt][3] + bv1);
            } else {
                float* Out = (float*)OutV;
                *(float2*)(Out + ((size_t)(b * Mtot + m0t + r0)    ) * HW + col) =
                    make_float2(acc[mt][nt][0] + bv0, acc[mt][nt][1] + bv0);
                *(float2*)(Out + ((size_t)(b * Mtot + m0t + r0 + 8)) * HW + col) =
                    make_float2(acc[mt][nt][2] + bv1, acc[mt][nt][3] + bv1);
            }
        }
    }
}

// =====================================================================
// warp-per-head windowed attention: one CTA (256 thr) per window, warp = head.
// =====================================================================
#define PH 136                     // smem pitch in halves (272B, conflict-free ldmatrix)
#define ATT_SMEM (3*64*PH*2)       // 52224

__global__ __launch_bounds__(256)
void attn_mma(const __half* __restrict__ qkv, __half* __restrict__ Ah)
{
    extern __shared__ __half asm_[];
    __half* qsm = asm_;                // [pos 64][128 c], pitch PH; reused as out-stage
    __half* ksm = asm_ + 64*PH;
    __half* vsm = asm_ + 128*PH;

    const int tid  = threadIdx.x;
    const int lane = tid & 31;
    const int wrp  = tid >> 5;         // head
    const int wi   = blockIdx.x;
    const int b    = wi >> 10;
    const int w    = wi & 1023;
    const int prow = (w >> 5) * 7, pcol = (w & 31) * 7;

    // zero pad rows 49..63 of q/k/v (NaN-safety for masked lanes)
    if (tid < 255){
        ((uint4*)(qsm + 49*PH))[tid] = make_uint4(0,0,0,0);
        ((uint4*)(ksm + 49*PH))[tid] = make_uint4(0,0,0,0);
        ((uint4*)(vsm + 49*PH))[tid] = make_uint4(0,0,0,0);
    }

    // ---- vectorized loads (aligned 64-half span per channel) ----
    const int w49    = w * 49;
    const int astart = w49 & ~7;
    const int off0   = astart - w49;
    const __half* qp = qkv + (size_t)(b * 384      ) * HW;
    const __half* kp = qkv + (size_t)(b * 384 + 128) * HW;
    const __half* vp = qkv + (size_t)(b * 384 + 256) * HW;
    const __half hscale = __float2half(0.25f);

    #pragma unroll
    for (int i = 0; i < 4; i++){
        int idx = tid + i * 256;
        int c = idx >> 3, piece = idx & 7;
        int p0 = off0 + piece * 8;
        size_t ga = (size_t)c * HW + astart + piece * 8;

        uint4 vq = *(const uint4*)(qp + ga);
        __half* hq = (__half*)&vq;
        #pragma unroll
        for (int j = 0; j < 8; j++){
            int p = p0 + j;
            if ((unsigned)p < 49u) qsm[p*PH + c] = __hmul(hq[j], hscale);
        }
        uint4 vk = *(const uint4*)(kp + ga);
        __half* hk = (__half*)&vk;
        #pragma unroll
        for (int j = 0; j < 8; j++){
            int p = p0 + j;
            if ((unsigned)p < 49u) ksm[p*PH + c] = hk[j];
        }
        uint4 vv = *(const uint4*)(vp + ga);
        __half* hv = (__half*)&vv;
        #pragma unroll
        for (int j = 0; j < 8; j++){
            int p = p0 + j;
            if ((unsigned)p < 49u) vsm[p*PH + c] = hv[j];
        }
    }
    __syncthreads();

    const uint32_t qsb = smem_u32(qsm), ksb = smem_u32(ksm), vsb = smem_u32(vsm);
    const int row8 = lane & 7, quad = lane >> 3;
    const int cbase = 2 * (lane & 3);
    const uint32_t hoff = (uint32_t)wrp * 32;

    uint32_t kf[2][2][4];
    #pragma unroll
    for (int g = 0; g < 2; g++){
        uint32_t ba = ksb + (uint32_t)((g*32 + quad*8 + row8) * (PH*2)) + hoff;
        LDSM_X4(kf[g][0][0], kf[g][0][1], kf[g][0][2], kf[g][0][3], ba);
        LDSM_X4(kf[g][1][0], kf[g][1][1], kf[g][1][2], kf[g][1][3], ba + 16);
    }
    uint32_t vf[4][4];
    #pragma unroll
    for (int ksp = 0; ksp < 4; ksp++){
        uint32_t va = vsb + (uint32_t)((ksp*16 + (lane & 15)) * (PH*2)) + hoff + ((lane >> 4) << 4);
        LDSM_X4T(vf[ksp][0], vf[ksp][1], vf[ksp][2], vf[ksp][3], va);
    }

    __half* ost = qsm;

    #pragma unroll
    for (int lt = 0; lt < 4; lt++){
        const int l0 = lt * 16;
        uint32_t af[4];
        LDSM_X4(af[0], af[1], af[2], af[3],
                qsb + (uint32_t)((l0 + ((quad & 1) << 3) + row8) * (PH*2)) + hoff + ((quad >> 1) << 4));

        float sc[8][4];
        #pragma unroll
        for (int nt = 0; nt < 8; nt++){
            sc[nt][0] = sc[nt][1] = sc[nt][2] = sc[nt][3] = 0.f;
            int g = nt >> 2, j = nt & 3;
            MMA_F16(sc[nt], af, kf[g][0][j], kf[g][1][j]);
        }

        float mx0 = -1e30f, mx1 = -1e30f;
        #pragma unroll
        for (int nt = 0; nt < 8; nt++){
            int col0 = nt*8 + cbase;
            if (col0 > 48){ sc[nt][0] = -1e30f; sc[nt][2] = -1e30f; }
            if (col0 + 1 > 48){ sc[nt][1] = -1e30f; sc[nt][3] = -1e30f; }
            mx0 = fmaxf(mx0, fmaxf(sc[nt][0], sc[nt][1]));
            mx1 = fmaxf(mx1, fmaxf(sc[nt][2], sc[nt][3]));
        }
        mx0 = fmaxf(mx0, __shfl_xor_sync(0xffffffffu, mx0, 1));
        mx0 = fmaxf(mx0, __shfl_xor_sync(0xffffffffu, mx0, 2));
        mx1 = fmaxf(mx1, __shfl_xor_sync(0xffffffffu, mx1, 1));
        mx1 = fmaxf(mx1, __shfl_xor_sync(0xffffffffu, mx1, 2));

        float s0 = 0.f, s1 = 0.f;
        #pragma unroll
        for (int nt = 0; nt < 8; nt++){
            sc[nt][0] = __expf(sc[nt][0] - mx0);
            sc[nt][1] = __expf(sc[nt][1] - mx0);
            sc[nt][2] = __expf(sc[nt][2] - mx1);
            sc[nt][3] = __expf(sc[nt][3] - mx1);
            s0 += sc[nt][0] + sc[nt][1];
            s1 += sc[nt][2] + sc[nt][3];
        }
        s0 += __shfl_xor_sync(0xffffffffu, s0, 1);
        s0 += __shfl_xor_sync(0xffffffffu, s0, 2);
        s1 += __shfl_xor_sync(0xffffffffu, s1, 1);
        s1 += __shfl_xor_sync(0xffffffffu, s1, 2);
        float inv0 = 1.f / s0, inv1 = 1.f / s1;

        float oc[2][4];
        oc[0][0]=oc[0][1]=oc[0][2]=oc[0][3]=0.f;
        oc[1][0]=oc[1][1]=oc[1][2]=oc[1][3]=0.f;
        #pragma unroll
        for (int ksp = 0; ksp < 4; ksp++){
            uint32_t pf[4];
            pf[0] = pack_h2(sc[2*ksp  ][0]*inv0, sc[2*ksp  ][1]*inv0);
            pf[1] = pack_h2(sc[2*ksp  ][2]*inv1, sc[2*ksp  ][3]*inv1);
            pf[2] = pack_h2(sc[2*ksp+1][0]*inv0, sc[2*ksp+1][1]*inv0);
            pf[3] = pack_h2(sc[2*ksp+1][2]*inv1, sc[2*ksp+1][3]*inv1);
            MMA_F16(oc[0], pf, vf[ksp][0], vf[ksp][1]);
            MMA_F16(oc[1], pf, vf[ksp][2], vf[ksp][3]);
        }

        int pr = l0 + (lane >> 2);
        #pragma unroll
        for (int n = 0; n < 2; n++){
            if (pr < 49)
                *(uint32_t*)(ost + pr*PH + wrp*16 + n*8 + cbase) = pack_h2(oc[n][0], oc[n][1]);
            if (pr + 8 < 49)
                *(uint32_t*)(ost + (pr+8)*PH + wrp*16 + n*8 + cbase) = pack_h2(oc[n][2], oc[n][3]);
        }
    }
    __syncthreads();

    for (int idx = tid; idx < 784; idx += 256){
        int p = idx >> 4, ch = idx & 15;
        int pix = (prow + p / 7) * 224 + pcol + (p % 7);
        int t = pix >> 7, n = pix & 127;
        *(uint4*)(Ah + (((size_t)(b * NTILE + t)) * 128 + n) * 128 + ch*8) =
            *(const uint4*)(ost + p*PH + ch*8);
    }
}

// ---------------- launch ----------------
extern "C" void kernel_launch(void* const* d_in, const int* in_sizes, int n_in,
                              void* d_out, int out_size)
{
    const float* x     = (const float*)d_in[0];
    const float* w_qkv = (const float*)d_in[1];
    const float* b_qkv = (const float*)d_in[2];
    const float* w_out = (const float*)d_in[3];
    const float* b_out = (const float*)d_in[4];
    float* out = (float*)d_out;

    __half *qkvh, *xh, *ah, *wh;
    cudaGetSymbolAddress((void**)&qkvh, g_qkvh);
    cudaGetSymbolAddress((void**)&xh, g_xh);
    cudaGetSymbolAddress((void**)&ah, g_ah);
    cudaGetSymbolAddress((void**)&wh, g_wh);

    cudaFuncSetAttribute(xconv,    cudaFuncAttributeMaxDynamicSharedMemorySize, XCONV_SMEM);
    cudaFuncSetAttribute(gemm_tc,  cudaFuncAttributeMaxDynamicSharedMemorySize, GEMM_SMEM);
    cudaFuncSetAttribute(attn_mma, cudaFuncAttributeMaxDynamicSharedMemorySize, ATT_SMEM);

    wconv<<<48, 256>>>(w_qkv, wh, 12288);
    wconv<<<16, 256>>>(w_out, wh + 49152, 4096);
    xconv<<<dim3(32, 2, 4), 256, XCONV_SMEM>>>(x, xh);
    gemm_tc<<<dim3(NTILE, 3, 4), 256, GEMM_SMEM>>>(wh, 0,     xh, b_qkv, qkvh, 384, 1);
    attn_mma<<<4096, 256, ATT_SMEM>>>(qkvh, ah);
    gemm_tc<<<dim3(NTILE, 1, 4), 256, GEMM_SMEM>>>(wh, 49152, ah, b_out, out, 128, 0);
}